// round 1
// baseline (speedup 1.0000x reference)
#include <cuda_runtime.h>
#include <math.h>
#include <stdint.h>

#define N_P 33600
#define N_G 256
#define N_C 80
#define KK  13

// ---------------- scratch (device globals; no runtime allocation) ----------
__device__ float g_iou [(size_t)N_G * N_P];   // column-major: [j*N_P + i]
__device__ float g_cost[(size_t)N_G * N_P];   // column-major
__device__ float g_lT  [(size_t)N_C * N_P];   // logits, class-major
__device__ float g_sT  [(size_t)N_C * N_P];   // sigmoid(logit), class-major
__device__ float g_mT  [(size_t)N_C * N_P];   // max(l,0)+log1p(exp(-|l|)), class-major
__device__ float4 g_gtbox [N_G];              // x1,y1,x2,y2
__device__ float4 g_gtmeta[N_G];              // area, cx, cy, pad
__device__ int    g_glab  [N_G];
__device__ unsigned char g_valid[N_P];
__device__ int    g_cnt [N_P];
__device__ int    g_mgt [N_P];
__device__ float  g_miou[N_P];

// ---------------- kernel G: GT preprocessing -------------------------------
__global__ void prep_gt_kernel(const float* __restrict__ gtb,
                               const int*   __restrict__ glab) {
    int j = threadIdx.x;
    if (j < N_G) {
        float x1 = gtb[j*4+0], y1 = gtb[j*4+1];
        float x2 = gtb[j*4+2], y2 = gtb[j*4+3];
        g_gtbox[j] = make_float4(x1, y1, x2, y2);
        float area = (x2 - x1) * (y2 - y1);
        float pad  = (x1 + y1 + x2 + y2) > 0.0f ? 1.0f : 0.0f;
        g_gtmeta[j] = make_float4(area, (x1 + x2) * 0.5f, (y1 + y2) * 0.5f, pad);
        g_glab[j] = glab[j];
    }
}

// ---------------- kernel S: per-(prior,class) sigmoid / softplus, transposed
__global__ void prep_scores_kernel(const float* __restrict__ ps) {
    int t = blockIdx.x * blockDim.x + threadIdx.x;
    if (t >= N_C * N_P) return;
    int c = t / N_P;
    int i = t - c * N_P;
    float l = ps[(size_t)i * N_C + c];
    float e = expf(-fabsf(l));
    float inv = __fdiv_rn(1.0f, 1.0f + e);
    float sig = (l >= 0.0f) ? inv : e * inv;     // sigmoid(l)
    float m = fmaxf(l, 0.0f) + log1pf(e);        // softplus part of BCE
    g_lT[t] = l;
    g_sT[t] = sig;
    g_mT[t] = m;
}

// ---------------- kernel V: valid mask (inside any GT) + zero counters -----
__global__ void valid_kernel(const float* __restrict__ priors) {
    int i = blockIdx.x * blockDim.x + threadIdx.x;
    if (i >= N_P) return;
    float px = priors[i*4+0], py = priors[i*4+1];
    bool any = false;
    for (int j = 0; j < N_G; j++) {
        float4 b = g_gtbox[j];
        float4 m = g_gtmeta[j];
        bool in = (px - b.x > 0.0f) && (py - b.y > 0.0f) &&
                  (b.z - px > 0.0f) && (b.w - py > 0.0f) &&
                  (m.w > 0.5f);
        any |= in;
    }
    g_valid[i] = any ? 1 : 0;
    g_cnt[i] = 0;
}

// ---------------- kernel A: pairwise IoU + cost (column-major store) -------
__global__ void pair_kernel(const float* __restrict__ priors,
                            const float* __restrict__ pb) {
    int i = blockIdx.x * blockDim.x + threadIdx.x;
    if (i >= N_P) return;
    int j0 = blockIdx.y * (N_G / 8);

    float px = priors[i*4+0], py = priors[i*4+1], st = priors[i*4+2];
    float ax1 = pb[i*4+0], ay1 = pb[i*4+1], ax2 = pb[i*4+2], ay2 = pb[i*4+3];
    float area_a = (ax2 - ax1) * (ay2 - ay1);
    bool valid = g_valid[i] != 0;

    #pragma unroll 4
    for (int jj = 0; jj < N_G / 8; jj++) {
        int j = j0 + jj;
        float4 b  = g_gtbox[j];
        float4 m4 = g_gtmeta[j];
        // IoU (computed for ALL pairs; feeds dynamic_ks)
        float ltx = fmaxf(ax1, b.x), lty = fmaxf(ay1, b.y);
        float rbx = fminf(ax2, b.z), rby = fminf(ay2, b.w);
        float w = fmaxf(rbx - ltx, 0.0f), h = fmaxf(rby - lty, 0.0f);
        float inter = w * h;
        float uni = area_a + m4.x - inter;
        float iou = __fdiv_rn(inter, fmaxf(uni, 1e-6f));
        g_iou[(size_t)j * N_P + i] = iou;

        float cost;
        if (valid) {
            float dx = px - m4.y, dy = py - m4.z;
            float dist = __fdiv_rn(__fsqrt_rn(dx*dx + dy*dy), st);
            float scp = expf((dist - 3.0f) * 2.302585092994046f); // 10^(dist-3)
            int lab = g_glab[j];
            size_t off = (size_t)lab * N_P + i;
            float l  = g_lT[off];
            float s  = g_sT[off];
            float mm = g_mT[off];
            float d = iou - s;
            float scale = d * d;
            float bce = mm - l * iou;
            float ic = -logf(iou + 1e-7f) * 3.0f;
            cost = (bce * scale + ic) + scp;
        } else {
            cost = 1e8f;   // INF per reference
        }
        g_cost[(size_t)j * N_P + i] = cost;
    }
}

// ---------------- kernel T: per-GT top-13 (iou sum -> ks, cost -> cands) ---
__global__ void topk_kernel() {
    int j = blockIdx.x;
    int tid = threadIdx.x;
    const float* __restrict__ iouc = g_iou  + (size_t)j * N_P;
    const float* __restrict__ cc   = g_cost + (size_t)j * N_P;

    // thread-local sorted lists
    float ti[KK];            // descending iou
    float tc[KK];            // ascending cost
    int   tx[KK];            // indices for tc
    #pragma unroll
    for (int k = 0; k < KK; k++) { ti[k] = -1.0f; tc[k] = 3.4e38f; tx[k] = 0; }

    for (int i = tid; i < N_P; i += 256) {
        float v = iouc[i];
        if (v > ti[KK-1]) {
            ti[KK-1] = v;
            #pragma unroll
            for (int k = KK-1; k > 0; k--) {
                if (ti[k] > ti[k-1]) { float t = ti[k-1]; ti[k-1] = ti[k]; ti[k] = t; }
            }
        }
        float c = cc[i];
        if (c < tc[KK-1]) {
            tc[KK-1] = c; tx[KK-1] = i;
            #pragma unroll
            for (int k = KK-1; k > 0; k--) {
                if (tc[k] < tc[k-1]) {
                    float t = tc[k-1]; tc[k-1] = tc[k]; tc[k] = t;
                    int   q = tx[k-1]; tx[k-1] = tx[k]; tx[k] = q;
                }
            }
        }
    }

    __shared__ float sv[256];
    __shared__ int   si[256];
    __shared__ int   cand[KK];

    // ---- global top-13 iou sum (argmax extraction, unique pop via tid tie-break)
    float iou_sum = 0.0f;
    for (int r = 0; r < KK; r++) {
        sv[tid] = ti[0]; si[tid] = tid;
        __syncthreads();
        for (int s = 128; s > 0; s >>= 1) {
            if (tid < s) {
                if (sv[tid+s] > sv[tid] || (sv[tid+s] == sv[tid] && si[tid+s] < si[tid])) {
                    sv[tid] = sv[tid+s]; si[tid] = si[tid+s];
                }
            }
            __syncthreads();
        }
        float best = sv[0]; int win = si[0];
        __syncthreads();
        iou_sum += best;
        if (tid == win) {
            #pragma unroll
            for (int k = 0; k < KK-1; k++) ti[k] = ti[k+1];
            ti[KK-1] = -1.0f;
        }
    }

    // ---- global 13 lowest-cost candidates (argmin extraction)
    for (int r = 0; r < KK; r++) {
        sv[tid] = tc[0]; si[tid] = tid;
        __syncthreads();
        for (int s = 128; s > 0; s >>= 1) {
            if (tid < s) {
                if (sv[tid+s] < sv[tid] || (sv[tid+s] == sv[tid] && si[tid+s] < si[tid])) {
                    sv[tid] = sv[tid+s]; si[tid] = si[tid+s];
                }
            }
            __syncthreads();
        }
        int win = si[0];
        __syncthreads();
        if (tid == win) {
            cand[r] = tx[0];
            #pragma unroll
            for (int k = 0; k < KK-1; k++) { tc[k] = tc[k+1]; tx[k] = tx[k+1]; }
            tc[KK-1] = 3.4e38f;
        }
        __syncthreads();
    }

    // dynamic_ks = clip(int(sum_topk_iou), 1, ...) ; effective cap at KK
    int ks = (int)iou_sum;           // truncation toward zero (sum >= 0)
    if (ks < 1)  ks = 1;
    if (ks > KK) ks = KK;

    if (tid < ks) {
        int i = cand[tid];
        atomicAdd(&g_cnt[i], 1);
        g_mgt[i]  = j;         // racy if multi, but multi path recomputes
        g_miou[i] = iouc[i];
    }
}

// ---------------- kernel R: resolve per-prior assignment -------------------
__global__ void resolve_kernel(float* __restrict__ out) {
    int i = blockIdx.x * blockDim.x + threadIdx.x;
    if (i >= N_P) return;
    int c = g_cnt[i];
    bool valid = g_valid[i] != 0;
    int gsel = 0;
    float iou = 0.0f;
    bool fg = false;
    if (c == 1) {
        gsel = g_mgt[i];
        iou  = g_miou[i];
        fg = true;
    } else if (c > 1) {
        // argmin over full cost row (ties -> lowest index, strict <)
        float best = g_cost[i];
        gsel = 0;
        for (int j = 1; j < N_G; j++) {
            float cj = g_cost[(size_t)j * N_P + i];
            if (cj < best) { best = cj; gsel = j; }
        }
        iou = g_iou[(size_t)gsel * N_P + i];
        fg = true;
    }
    bool fin = fg && valid;
    out[i]          = fin ? (float)(gsel + 1)      : 0.0f;
    out[N_P + i]    = fin ? iou                    : -1e8f;
    out[2*N_P + i]  = fin ? (float)g_glab[gsel]    : -1.0f;
}

// ---------------- launch ----------------------------------------------------
extern "C" void kernel_launch(void* const* d_in, const int* in_sizes, int n_in,
                              void* d_out, int out_size) {
    const float* pred_scores = (const float*)d_in[0];
    const float* priors      = (const float*)d_in[1];
    const float* pred_bboxes = (const float*)d_in[2];
    const float* gt_bboxes   = (const float*)d_in[3];
    const int*   gt_labels   = (const int*)  d_in[4];  // jax default x64 off -> int32

    prep_gt_kernel<<<1, 256>>>(gt_bboxes, gt_labels);
    prep_scores_kernel<<<(N_C * N_P + 255) / 256, 256>>>(pred_scores);
    valid_kernel<<<(N_P + 255) / 256, 256>>>(priors);
    dim3 gA((N_P + 255) / 256, 8);
    pair_kernel<<<gA, 256>>>(priors, pred_bboxes);
    topk_kernel<<<N_G, 256>>>();
    resolve_kernel<<<(N_P + 255) / 256, 256>>>((float*)d_out);
}